// round 15
// baseline (speedup 1.0000x reference)
#include <cuda_runtime.h>
#include <cuda_fp16.h>
#include <math.h>
#include <stdint.h>

#define B_   2
#define S_   2048
#define H_   2048
#define NH_  16
#define NKV_ 4
#define DH_  128
#define I_   8192
#define M_   (B_ * S_)          // 4096 tokens
#define GROUPS_ (NH_ / NKV_)    // 4
#define EPS_ 1e-6f

#define QKV_N_ 3072
#define GU_N_  16384            // slot space: 16-slot groups = 8 gate cols + 8 up cols

// ---------------- scratch (device globals; no runtime allocation) ----------------
__device__ __half g_xnorm16[(size_t)M_ * H_];
__device__ __half g_q16[(size_t)B_ * NH_ * S_ * DH_];    // (b,h,s,d)
__device__ __half g_k16[(size_t)B_ * NKV_ * S_ * DH_];   // (b,kvh,s,d)
__device__ __half g_v16[(size_t)B_ * NKV_ * S_ * DH_];   // (b,kvh,s,d)
__device__ __half g_attn16[(size_t)M_ * H_];
__device__ float  g_h1[(size_t)M_ * H_];
__device__ __half g_x216[(size_t)M_ * H_];
__device__ __half g_act16[(size_t)M_ * I_];
// fp16 weights, SAME [K][N] layout as inputs (no transpose)
__device__ __half w16q[(size_t)H_ * H_];
__device__ __half w16k[(size_t)H_ * 512];
__device__ __half w16v[(size_t)H_ * 512];
__device__ __half w16o[(size_t)H_ * H_];
__device__ __half w16g[(size_t)H_ * I_];
__device__ __half w16u[(size_t)H_ * I_];
__device__ __half w16d[(size_t)I_ * H_];

// ---------------- helpers ----------------
__device__ __forceinline__ uint32_t smem_u32(const void* p) {
    return (uint32_t)__cvta_generic_to_shared(p);
}
__device__ __forceinline__ void cp_async16(uint32_t dst, const void* src) {
    asm volatile("cp.async.cg.shared.global [%0], [%1], 16;\n" :: "r"(dst), "l"(src));
}
__device__ __forceinline__ void cp_commit() { asm volatile("cp.async.commit_group;\n"); }
__device__ __forceinline__ void cp_wait0()  { asm volatile("cp.async.wait_group 0;\n"); }
__device__ __forceinline__ void cp_wait1()  { asm volatile("cp.async.wait_group 1;\n"); }

__device__ __forceinline__ void mma_f16(float* d, const uint32_t* a, uint32_t b0, uint32_t b1) {
    asm volatile(
        "mma.sync.aligned.m16n8k16.row.col.f32.f16.f16.f32 "
        "{%0,%1,%2,%3}, {%4,%5,%6,%7}, {%8,%9}, {%0,%1,%2,%3};\n"
        : "+f"(d[0]), "+f"(d[1]), "+f"(d[2]), "+f"(d[3])
        : "r"(a[0]), "r"(a[1]), "r"(a[2]), "r"(a[3]), "r"(b0), "r"(b1));
}

__device__ __forceinline__ uint32_t packh(float a, float b) {
    __half2 h = __floats2half2_rn(a, b);
    return *(uint32_t*)&h;
}

// ---------------- streaming fp32 -> fp16 convert for ALL weights, one launch ----------------
// chunk = 8 elements. cumulative chunk counts decode the segment.
#define CVT_CHUNKS 7602176L
__global__ __launch_bounds__(256) void cvt_all(
    const float* __restrict__ wq, const float* __restrict__ wk, const float* __restrict__ wv,
    const float* __restrict__ wo, const float* __restrict__ wg, const float* __restrict__ wu,
    const float* __restrict__ wd,
    __half* __restrict__ oq, __half* __restrict__ ok, __half* __restrict__ ov,
    __half* __restrict__ oo, __half* __restrict__ og, __half* __restrict__ ou,
    __half* __restrict__ od) {
    long i = (long)blockIdx.x * 256 + threadIdx.x;
    if (i >= CVT_CHUNKS) return;
    const float* src; __half* dst; long off;
    if (i < 524288L)        { src = wq; dst = oq; off = i; }
    else if (i < 655360L)   { src = wk; dst = ok; off = i - 524288L; }
    else if (i < 786432L)   { src = wv; dst = ov; off = i - 655360L; }
    else if (i < 1310720L)  { src = wo; dst = oo; off = i - 786432L; }
    else if (i < 3407872L)  { src = wg; dst = og; off = i - 1310720L; }
    else if (i < 5505024L)  { src = wu; dst = ou; off = i - 3407872L; }
    else                    { src = wd; dst = od; off = i - 5505024L; }
    const float4* s4 = (const float4*)(src + off * 8);
    float4 a = s4[0], b = s4[1];
    uint4 o4 = make_uint4(packh(a.x, a.y), packh(a.z, a.w),
                          packh(b.x, b.y), packh(b.z, b.w));
    *(uint4*)(dst + off * 8) = o4;
}
#define CVT_BLOCKS ((int)((CVT_CHUNKS + 255) / 256))

// ---------------- RMSNorm: fp32 in, fp16 out ----------------
__global__ void rmsnorm_kernel(const float* __restrict__ x, const float* __restrict__ w,
                               __half* __restrict__ y, int Hdim) {
    int row = blockIdx.x;
    const float4* xr = (const float4*)(x + (size_t)row * Hdim);
    uint2* yr = (uint2*)(y + (size_t)row * Hdim);
    const float4* wv = (const float4*)w;
    int n4 = Hdim >> 2;

    float ss = 0.f;
    for (int i = threadIdx.x; i < n4; i += blockDim.x) {
        float4 v = xr[i];
        ss += v.x * v.x + v.y * v.y + v.z * v.z + v.w * v.w;
    }
    __shared__ float wsum[8];
    for (int o = 16; o > 0; o >>= 1) ss += __shfl_xor_sync(0xffffffffu, ss, o);
    int warp = threadIdx.x >> 5;
    if ((threadIdx.x & 31) == 0) wsum[warp] = ss;
    __syncthreads();
    __shared__ float s_inv;
    if (threadIdx.x == 0) {
        float t = 0.f;
        #pragma unroll
        for (int i = 0; i < 8; i++) t += wsum[i];
        s_inv = rsqrtf(t / (float)Hdim + EPS_);
    }
    __syncthreads();
    float inv = s_inv;
    for (int i = threadIdx.x; i < n4; i += blockDim.x) {
        float4 v = xr[i];
        float4 ww = wv[i];
        uint2 o;
        o.x = packh(v.x * inv * ww.x, v.y * inv * ww.y);
        o.y = packh(v.z * inv * ww.z, v.w * inv * ww.w);
        yr[i] = o;
    }
}

// ---------------- fused q/k RMSNorm + RoPE: one WARP per (token, head), in place ----------------
__global__ __launch_bounds__(256) void qknorm_rope_kernel(
        __half* __restrict__ q16, __half* __restrict__ k16,
        const float* __restrict__ qnw, const float* __restrict__ knw,
        const float* __restrict__ cosp, const float* __restrict__ sinp) {
    int wid = threadIdx.x >> 5, lane = threadIdx.x & 31;
    int gw = blockIdx.x * 8 + wid;
    int hs = gw >> 12;
    int token = gw & 4095;
    int b = token >> 11, sq = token & 2047;

    __half* p;
    const float* w;
    float outScale;
    if (hs < NH_) {
        p = q16 + (((size_t)b * NH_ + hs) * S_ + sq) * DH_;
        w = qnw; outScale = 0.08838834764831845f;
    } else {
        p = k16 + (((size_t)b * NKV_ + (hs - NH_)) * S_ + sq) * DH_;
        w = knw; outScale = 1.0f;
    }

    int d = lane * 4;
    uint2 raw = *(const uint2*)(p + d);
    __half2 h01 = *(__half2*)&raw.x;
    __half2 h23 = *(__half2*)&raw.y;
    float v0 = __half2float(__low2half(h01)), v1 = __half2float(__high2half(h01));
    float v2 = __half2float(__low2half(h23)), v3 = __half2float(__high2half(h23));

    float ss = v0 * v0 + v1 * v1 + v2 * v2 + v3 * v3;
    #pragma unroll
    for (int o = 16; o > 0; o >>= 1) ss += __shfl_xor_sync(0xffffffffu, ss, o);
    float inv = rsqrtf(ss * (1.0f / (float)DH_) + EPS_);

    float4 ww = *(const float4*)(w + d);
    float n0 = v0 * inv * ww.x, n1 = v1 * inv * ww.y;
    float n2 = v2 * inv * ww.z, n3 = v3 * inv * ww.w;

    float o0 = __shfl_xor_sync(0xffffffffu, n0, 16);
    float o1 = __shfl_xor_sync(0xffffffffu, n1, 16);
    float o2 = __shfl_xor_sync(0xffffffffu, n2, 16);
    float o3 = __shfl_xor_sync(0xffffffffu, n3, 16);
    float sign = (lane < 16) ? -1.0f : 1.0f;

    float4 cv = *(const float4*)(cosp + (size_t)token * DH_ + d);
    float4 sv = *(const float4*)(sinp + (size_t)token * DH_ + d);

    float r0 = (n0 * cv.x + sign * o0 * sv.x) * outScale;
    float r1 = (n1 * cv.y + sign * o1 * sv.y) * outScale;
    float r2 = (n2 * cv.z + sign * o2 * sv.z) * outScale;
    float r3 = (n3 * cv.w + sign * o3 * sv.w) * outScale;

    uint2 outp;
    outp.x = packh(r0, r1);
    outp.y = packh(r2, r3);
    *(uint2*)(p + d) = outp;
}

// ---------------- fp16 tensor-core GEMM: K-major B + ldmatrix.trans ----------------
// 256 thr, 128x256 tile, BK=64, 3-stage. A smem [128][72] row-major-k; B smem [64 k][264 n-slots].
// MODE 0: fp32 C (+opt Res), B = Bq, stride N.
// MODE 1: gate/up 8-col-group interleave (Bq=gate, Bk=up, stride 8192) -> silu -> C16 width N/2.
// MODE 3: QKV column routing (Bq/Bk/Bv, strides 2048/512/512) -> head-major q/k/v (C16/Ck/Cv).
#define GPA 72
#define GPB 264
#define G_ASZ (128 * GPA)
#define G_BSZ (64 * GPB)
#define G_STAGE (G_ASZ + G_BSZ)                    // 26112 halves = 52224 B
#define G_NSTAGE 3
#define GEMM_SMEM_BYTES (G_NSTAGE * G_STAGE * 2)   // 156672 B

template<int MODE>
__device__ __forceinline__ void gemm_issue(const __half* __restrict__ A, long K, long rowBase,
                                           const __half* __restrict__ Bq,
                                           const __half* __restrict__ Bk,
                                           const __half* __restrict__ Bv,
                                           long colBase, long N,
                                           __half* As, __half* Bs, int tid, int k0) {
    // A: 128 rows x 64 halves; thread t: row t/2, half-row t%2
    {
        int r = tid >> 1, hf = tid & 1;
        uint32_t dst = smem_u32(As + r * GPA + hf * 32);
        const __half* src = A + (rowBase + r) * K + k0 + hf * 32;
        #pragma unroll
        for (int i = 0; i < 4; i++) cp_async16(dst + i * 16, src + i * 8);
    }
    // B: 64 k-rows x 256 n-slots, 8-col (16B) chunks: 2048 chunks / 256 thr = 8 each
    #pragma unroll
    for (int p = 0; p < 8; p++) {
        int f = tid + p * 256;
        int kr = f >> 5, nc8 = (f & 31) * 8;
        const __half* src;
        if (MODE == 3) {
            long c = colBase + nc8;
            if (c < 2048)      src = Bq + (size_t)(k0 + kr) * 2048 + c;
            else if (c < 2560) src = Bk + (size_t)(k0 + kr) * 512 + (c - 2048);
            else               src = Bv + (size_t)(k0 + kr) * 512 + (c - 2560);
        } else if (MODE == 1) {
            long g = (colBase + nc8) >> 4;
            src = ((nc8 & 15) < 8 ? Bq : Bk) + (size_t)(k0 + kr) * 8192 + g * 8;
        } else {
            src = Bq + (size_t)(k0 + kr) * N + colBase + nc8;
        }
        cp_async16(smem_u32(Bs + kr * GPB + nc8), src);
    }
}

__device__ __forceinline__ void gemm_compute(const __half* As, const __half* Bs,
                                             int wm, int wn, int gid, int tig,
                                             int lrow, int lsel,
                                             float (&acc)[4][8][4]) {
    #pragma unroll
    for (int kk = 0; kk < 64; kk += 16) {
        uint32_t a[4][4];
        #pragma unroll
        for (int mi = 0; mi < 4; mi++) {
            const __half* ap = As + (wm + mi * 16 + gid) * GPA + kk + tig * 2;
            a[mi][0] = *(const uint32_t*)(ap);
            a[mi][1] = *(const uint32_t*)(ap + 8 * GPA);
            a[mi][2] = *(const uint32_t*)(ap + 8);
            a[mi][3] = *(const uint32_t*)(ap + 8 * GPA + 8);
        }
        uint32_t bbase = smem_u32(Bs + (kk + lrow) * GPB + wn + lsel * 8);
        #pragma unroll
        for (int cg = 0; cg < 4; cg++) {
            uint32_t r0, r1, r2, r3;
            asm volatile(
                "ldmatrix.sync.aligned.m8n8.x4.trans.shared.b16 {%0,%1,%2,%3}, [%4];"
                : "=r"(r0), "=r"(r1), "=r"(r2), "=r"(r3)
                : "r"(bbase + cg * 32u));
            #pragma unroll
            for (int mi = 0; mi < 4; mi++) {
                mma_f16(acc[mi][2 * cg],     a[mi], r0, r1);
                mma_f16(acc[mi][2 * cg + 1], a[mi], r2, r3);
            }
        }
    }
}

__device__ __forceinline__ float silu_mul(float g, float u) {
    return g / (1.f + __expf(-g)) * u;
}

template<int MODE>
__global__ __launch_bounds__(256, 1) void gemm_f16(const __half* __restrict__ A,
                                                   const __half* __restrict__ Bq,
                                                   const __half* __restrict__ Bk,
                                                   const __half* __restrict__ Bv,
                                                   const float* __restrict__ Res,
                                                   float* __restrict__ C,
                                                   __half* __restrict__ C16,
                                                   __half* __restrict__ Ck,
                                                   __half* __restrict__ Cv,
                                                   int N, int K) {
    extern __shared__ __half smh[];
    int tid = threadIdx.x;
    int wid = tid >> 5, lane = tid & 31;
    int gid = lane >> 2, tig = lane & 3;
    int lrow = lane & 15, lsel = lane >> 4;
    int wm = (wid >> 2) * 64, wn = (wid & 3) * 64;

    // CTA raster swizzle: 8-column groups for L2 locality
    int gx = gridDim.x, gy = gridDim.y;
    int bid = blockIdx.y * gx + blockIdx.x;
    int grpW = 8 * gy;
    int g8 = bid / grpW, r8 = bid % grpW;
    int wcols = min(8, gx - g8 * 8);
    int bxx = g8 * 8 + r8 % wcols;
    int byy = r8 / wcols;

    long rowBase = (long)byy * 128;
    long colBase = (long)bxx * 256;

    float acc[4][8][4] = {};

    __half* As[G_NSTAGE];
    __half* Bs[G_NSTAGE];
    #pragma unroll
    for (int s = 0; s < G_NSTAGE; s++) {
        As[s] = smh + s * G_STAGE;
        Bs[s] = As[s] + G_ASZ;
    }

    int nIter = K / 64;
    gemm_issue<MODE>(A, K, rowBase, Bq, Bk, Bv, colBase, N, As[0], Bs[0], tid, 0);
    cp_commit();
    gemm_issue<MODE>(A, K, rowBase, Bq, Bk, Bv, colBase, N, As[1], Bs[1], tid, 64);
    cp_commit();

    for (int it = 0; it < nIter; it++) {
        if (it + 1 < nIter) cp_wait1(); else cp_wait0();
        __syncthreads();
        if (it + 2 < nIter) {
            int s = (it + 2) % 3;
            gemm_issue<MODE>(A, K, rowBase, Bq, Bk, Bv, colBase, N, As[s], Bs[s], tid, (it + 2) * 64);
            cp_commit();
        }
        gemm_compute(As[it % 3], Bs[it % 3], wm, wn, gid, tig, lrow, lsel, acc);
    }

    if (MODE == 0) {
        #pragma unroll
        for (int mi = 0; mi < 4; mi++) {
            #pragma unroll
            for (int ni = 0; ni < 8; ni++) {
                long r0 = rowBase + wm + mi * 16 + gid;
                long c = colBase + wn + ni * 8 + tig * 2;
                float2 v0 = make_float2(acc[mi][ni][0], acc[mi][ni][1]);
                float2 v1 = make_float2(acc[mi][ni][2], acc[mi][ni][3]);
                if (Res != nullptr) {
                    float2 r0v = *(const float2*)(Res + r0 * N + c);
                    float2 r1v = *(const float2*)(Res + (r0 + 8) * N + c);
                    v0.x += r0v.x; v0.y += r0v.y;
                    v1.x += r1v.x; v1.y += r1v.y;
                }
                *(float2*)(C + r0 * N + c) = v0;
                *(float2*)(C + (r0 + 8) * N + c) = v1;
            }
        }
    } else if (MODE == 1) {
        // ni even = gate (group offset 0-7), ni odd = up (offset 8-15); same j per pair
        #pragma unroll
        for (int mi = 0; mi < 4; mi++) {
            #pragma unroll
            for (int t = 0; t < 4; t++) {
                long r0 = rowBase + wm + mi * 16 + gid;
                long j = (((colBase + wn) >> 4) + t) * 8 + tig * 2;
                float g0 = acc[mi][2 * t][0], g1 = acc[mi][2 * t][1];
                float g2 = acc[mi][2 * t][2], g3 = acc[mi][2 * t][3];
                float u0 = acc[mi][2 * t + 1][0], u1 = acc[mi][2 * t + 1][1];
                float u2 = acc[mi][2 * t + 1][2], u3 = acc[mi][2 * t + 1][3];
                *(uint32_t*)(C16 + r0 * (N / 2) + j) = packh(silu_mul(g0, u0), silu_mul(g1, u1));
                *(uint32_t*)(C16 + (r0 + 8) * (N / 2) + j) = packh(silu_mul(g2, u2), silu_mul(g3, u3));
            }
        }
    } else {
        // MODE 3: QKV head-major routing
        #pragma unroll
        for (int mi = 0; mi < 4; mi++) {
            #pragma unroll
            for (int ni = 0; ni < 8; ni++) {
                int c = (int)(colBase + wn + ni * 8 + tig * 2);
                #pragma unroll
                for (int half2i = 0; half2i < 2; half2i++) {
                    long tok = rowBase + wm + mi * 16 + gid + half2i * 8;
                    int b = (int)(tok >> 11), sq = (int)(tok & 2047);
                    uint32_t pk = packh(acc[mi][ni][half2i * 2], acc[mi][ni][half2i * 2 + 1]);
                    __half* dst;
                    if (c < 2048) {
                        int hh = c >> 7, d = c & 127;
                        dst = C16 + (((size_t)b * NH_ + hh) * S_ + sq) * DH_ + d;
                    } else if (c < 2560) {
                        int hh = (c - 2048) >> 7, d = c & 127;
                        dst = Ck + (((size_t)b * NKV_ + hh) * S_ + sq) * DH_ + d;
                    } else {
                        int hh = (c - 2560) >> 7, d = c & 127;
                        dst = Cv + (((size_t)b * NKV_ + hh) * S_ + sq) * DH_ + d;
                    }
                    *(uint32_t*)dst = pk;
                }
            }
        }
    }
}

// ---------------- fp16 flash attention: 64-row q blocks, 128 thr, 2 CTAs/SM ----------------
#define AST 136
#define AT_STAGE (2 * 64 * AST)
#define AT_SMEM_BYTES (2 * AT_STAGE * 2)     // 69632 B

__global__ __launch_bounds__(128, 2) void attn_kernel(const __half* __restrict__ q16,
                                                      const __half* __restrict__ k16,
                                                      const __half* __restrict__ v16,
                                                      __half* __restrict__ o) {
    extern __shared__ __half smh[];

    int qb = blockIdx.x, h = blockIdx.y, b = blockIdx.z;
    int kvh = h / GROUPS_;
    int tid = threadIdx.x;
    int w = tid >> 5, lane = tid & 31;
    int gid = lane >> 2, tig = lane & 3;
    int wq = w * 16;
    long bS = (long)b * S_;

    const __half* qh = q16 + (((size_t)b * NH_ + h) * S_ + (size_t)qb * 64) * DH_;
    const __half* kh = k16 + (((size_t)b * NKV_ + kvh) * S_) * DH_;
    const __half* vh = v16 + (((size_t)b * NKV_ + kvh) * S_) * DH_;

    __half* Qs = smh;
    for (int i = tid; i < 64 * 16; i += 128) {
        int r = i >> 4, c8 = (i & 15) * 8;
        *(uint4*)(Qs + r * AST + c8) = *(const uint4*)(qh + r * DH_ + c8);
    }
    __syncthreads();
    uint32_t qf[8][4];
    #pragma unroll
    for (int kk = 0; kk < 8; kk++) {
        const __half* qp = Qs + (wq + gid) * AST + kk * 16 + tig * 2;
        qf[kk][0] = *(const uint32_t*)(qp);
        qf[kk][1] = *(const uint32_t*)(qp + 8 * AST);
        qf[kk][2] = *(const uint32_t*)(qp + 8);
        qf[kk][3] = *(const uint32_t*)(qp + 8 * AST + 8);
    }
    __syncthreads();

    float of[16][4] = {};
    float m0 = -INFINITY, m1 = -INFINITY, l0 = 0.f, l1 = 0.f;

    int lrow = lane & 15, lsel = lane >> 4;

    {
        __half* Ks = smh;
        __half* Vs = smh + 64 * AST;
        #pragma unroll
        for (int p = 0; p < 8; p++) {
            int f = tid + p * 128;
            int r = f >> 4, c8 = (f & 15) * 8;
            cp_async16(smem_u32(Ks + r * AST + c8), kh + r * DH_ + c8);
            cp_async16(smem_u32(Vs + r * AST + c8), vh + r * DH_ + c8);
        }
        cp_commit();
    }

    const int nTiles = S_ / 64;
    for (int kt = 0; kt < nTiles; kt++) {
        if (kt + 1 < nTiles) {
            __half* Kn = smh + ((kt + 1) & 1) * AT_STAGE;
            __half* Vn = Kn + 64 * AST;
            const __half* kb = kh + (size_t)(kt + 1) * 64 * DH_;
            const __half* vb = vh + (size_t)(kt + 1) * 64 * DH_;
            #pragma unroll
            for (int p = 0; p < 8; p++) {
                int f = tid + p * 128;
                int r = f >> 4, c8 = (f & 15) * 8;
                cp_async16(smem_u32(Kn + r * AST + c8), kb + r * DH_ + c8);
                cp_async16(smem_u32(Vn + r * AST + c8), vb + r * DH_ + c8);
            }
            cp_commit();
            cp_wait1();
        } else {
            cp_wait0();
        }
        __syncthreads();

        const __half* Ks = smh + (kt & 1) * AT_STAGE;
        const __half* Vs = Ks + 64 * AST;

        float sc[8][4] = {};
        #pragma unroll
        for (int kk = 0; kk < 8; kk++) {
            #pragma unroll
            for (int ni = 0; ni < 8; ni++) {
                const __half* kp = Ks + (ni * 8 + gid) * AST + kk * 16 + tig * 2;
                uint32_t b0 = *(const uint32_t*)(kp);
                uint32_t b1 = *(const uint32_t*)(kp + 8);
                mma_f16(sc[ni], qf[kk], b0, b1);
            }
        }

        float mx0 = -INFINITY, mx1 = -INFINITY;
        #pragma unroll
        for (int ni = 0; ni < 8; ni++) {
            mx0 = fmaxf(mx0, fmaxf(sc[ni][0], sc[ni][1]));
            mx1 = fmaxf(mx1, fmaxf(sc[ni][2], sc[ni][3]));
        }
        mx0 = fmaxf(mx0, __shfl_xor_sync(0xffffffffu, mx0, 1));
        mx0 = fmaxf(mx0, __shfl_xor_sync(0xffffffffu, mx0, 2));
        mx1 = fmaxf(mx1, __shfl_xor_sync(0xffffffffu, mx1, 1));
        mx1 = fmaxf(mx1, __shfl_xor_sync(0xffffffffu, mx1, 2));
        float nm0 = fmaxf(m0, mx0), nm1 = fmaxf(m1, mx1);
        float s0 = 0.f, s1 = 0.f;
        #pragma unroll
        for (int ni = 0; ni < 8; ni++) {
            float e0 = __half2float(__float2half_rn(__expf(sc[ni][0] - nm0)));
            float e1 = __half2float(__float2half_rn(__expf(sc[ni][1] - nm0)));
            float e2 = __half2float(__float2half_rn(__expf(sc[ni][2] - nm1)));
            float e3 = __half2float(__float2half_rn(__expf(sc[ni][3] - nm1)));
            sc[ni][0] = e0; sc[ni][1] = e1; sc[ni][2] = e2; sc[ni][3] = e3;
            s0 += e0 + e1; s1 += e2 + e3;
        }
        s0 += __shfl_xor_sync(0xffffffffu, s0, 1);
        s0 += __shfl_xor_sync(0xffffffffu, s0, 2);
        s1 += __shfl_xor_sync(0xffffffffu, s1, 1);
        s1 += __shfl_xor_sync(0xffffffffu, s1, 2);
        float a0 = __expf(m0 - nm0), a1 = __expf(m1 - nm1);
        l0 = l0 * a0 + s0; l1 = l1 * a1 + s1;
        m0 = nm0; m1 = nm1;
        #pragma unroll
        for (int ni = 0; ni < 16; ni++) {
            of[ni][0] *= a0; of[ni][1] *= a0;
            of[ni][2] *= a1; of[ni][3] *= a1;
        }

        #pragma unroll
        for (int t = 0; t < 4; t++) {
            uint32_t pa[4];
            pa[0] = packh(sc[2 * t][0], sc[2 * t][1]);
            pa[1] = packh(sc[2 * t][2], sc[2 * t][3]);
            pa[2] = packh(sc[2 * t + 1][0], sc[2 * t + 1][1]);
            pa[3] = packh(sc[2 * t + 1][2], sc[2 * t + 1][3]);
            uint32_t vbase = smem_u32(Vs + (t * 16 + lrow) * AST + lsel * 8);
            #pragma unroll
            for (int ni2 = 0; ni2 < 8; ni2++) {
                uint32_t r0, r1, r2, r3;
                asm volatile(
                    "ldmatrix.sync.aligned.m8n8.x4.trans.shared.b16 {%0,%1,%2,%3}, [%4];"
                    : "=r"(r0), "=r"(r1), "=r"(r2), "=r"(r3)
                    : "r"(vbase + ni2 * 32u));
                mma_f16(of[2 * ni2], pa, r0, r1);
                mma_f16(of[2 * ni2 + 1], pa, r2, r3);
            }
        }
        __syncthreads();
    }

    float inv0 = 1.f / l0, inv1 = 1.f / l1;
    long r0 = bS + (long)qb * 64 + wq + gid;
    long r1 = r0 + 8;
    #pragma unroll
    for (int nt = 0; nt < 16; nt++) {
        int d = nt * 8 + tig * 2;
        *(uint32_t*)(o + (r0 * NH_ + h) * DH_ + d) = packh(of[nt][0] * inv0, of[nt][1] * inv0);
        *(uint32_t*)(o + (r1 * NH_ + h) * DH_ + d) = packh(of[nt][2] * inv1, of[nt][3] * inv1);
    }
}

// ---------------- launch ----------------
extern "C" void kernel_launch(void* const* d_in, const int* in_sizes, int n_in,
                              void* d_out, int out_size) {
    const float* hidden = (const float*)d_in[0];
    const float* cosp   = (const float*)d_in[1];
    const float* sinp   = (const float*)d_in[2];
    const float* wq     = (const float*)d_in[3];
    const float* wk     = (const float*)d_in[4];
    const float* wv     = (const float*)d_in[5];
    const float* wo     = (const float*)d_in[6];
    const float* qnw    = (const float*)d_in[7];
    const float* knw    = (const float*)d_in[8];
    const float* anw    = (const float*)d_in[9];
    const float* mnw    = (const float*)d_in[10];
    const float* wgate  = (const float*)d_in[11];
    const float* wup    = (const float*)d_in[12];
    const float* wdown  = (const float*)d_in[13];
    float* out = (float*)d_out;

    __half *xnorm, *q16, *k16, *v16, *attn, *x2, *act;
    __half *Wq, *Wk, *Wv, *Wo, *Wg, *Wu, *Wd;
    float *h1;
    cudaGetSymbolAddress((void**)&xnorm, g_xnorm16);
    cudaGetSymbolAddress((void**)&q16, g_q16);
    cudaGetSymbolAddress((void**)&k16, g_k16);
    cudaGetSymbolAddress((void**)&v16, g_v16);
    cudaGetSymbolAddress((void**)&attn, g_attn16);
    cudaGetSymbolAddress((void**)&h1, g_h1);
    cudaGetSymbolAddress((void**)&x2, g_x216);
    cudaGetSymbolAddress((void**)&act, g_act16);
    cudaGetSymbolAddress((void**)&Wq, w16q);
    cudaGetSymbolAddress((void**)&Wk, w16k);
    cudaGetSymbolAddress((void**)&Wv, w16v);
    cudaGetSymbolAddress((void**)&Wo, w16o);
    cudaGetSymbolAddress((void**)&Wg, w16g);
    cudaGetSymbolAddress((void**)&Wu, w16u);
    cudaGetSymbolAddress((void**)&Wd, w16d);

    cudaFuncSetAttribute(attn_kernel, cudaFuncAttributeMaxDynamicSharedMemorySize, AT_SMEM_BYTES);
    cudaFuncSetAttribute(gemm_f16<0>, cudaFuncAttributeMaxDynamicSharedMemorySize, GEMM_SMEM_BYTES);
    cudaFuncSetAttribute(gemm_f16<1>, cudaFuncAttributeMaxDynamicSharedMemorySize, GEMM_SMEM_BYTES);
    cudaFuncSetAttribute(gemm_f16<3>, cudaFuncAttributeMaxDynamicSharedMemorySize, GEMM_SMEM_BYTES);

    // 0) streaming fp32->fp16 convert of all weights (no transpose)
    cvt_all<<<CVT_BLOCKS, 256>>>(wq, wk, wv, wo, wgate, wup, wdown,
                                 Wq, Wk, Wv, Wo, Wg, Wu, Wd);

    // 1) attn rmsnorm (fp16 out)
    rmsnorm_kernel<<<M_, 256>>>(hidden, anw, xnorm, H_);

    // 2) fused QKV projection -> head-major q16/k16/v16
    gemm_f16<3><<<dim3(QKV_N_ / 256, M_ / 128), 256, GEMM_SMEM_BYTES>>>(
        xnorm, Wq, Wk, Wv, nullptr, nullptr, q16, k16, v16, QKV_N_, H_);

    // 3) fused q/k norm + rope, warp-per-head, in place
    qknorm_rope_kernel<<<M_ * (NH_ + NKV_) / 8, 256>>>(q16, k16, qnw, knw, cosp, sinp);

    // 4) attention (fp16 mma, 64-row blocks, 2 CTAs/SM)
    attn_kernel<<<dim3(S_ / 64, NH_, B_), 128, AT_SMEM_BYTES>>>(q16, k16, v16, attn);

    // 5) O projection + residual (fp32 out)
    gemm_f16<0><<<dim3(H_ / 256, M_ / 128), 256, GEMM_SMEM_BYTES>>>(
        attn, Wo, nullptr, nullptr, hidden, h1, nullptr, nullptr, nullptr, H_, H_);

    // 6) mlp rmsnorm (fp16 out)
    rmsnorm_kernel<<<M_, 256>>>(h1, mnw, x2, H_);

    // 7) fused gate+up projection, silu fused (fp16 act out)
    gemm_f16<1><<<dim3(GU_N_ / 256, M_ / 128), 256, GEMM_SMEM_BYTES>>>(
        x2, Wg, Wu, nullptr, nullptr, nullptr, act, nullptr, nullptr, GU_N_, H_);

    // 8) down projection + residual -> output (fp32)
    gemm_f16<0><<<dim3(H_ / 256, M_ / 128), 256, GEMM_SMEM_BYTES>>>(
        act, Wd, nullptr, nullptr, h1, out, nullptr, nullptr, nullptr, H_, I_);
}

// round 16
// speedup vs baseline: 1.0831x; 1.0831x over previous
#include <cuda_runtime.h>
#include <cuda_fp16.h>
#include <math.h>
#include <stdint.h>

#define B_   2
#define S_   2048
#define H_   2048
#define NH_  16
#define NKV_ 4
#define DH_  128
#define I_   8192
#define M_   (B_ * S_)          // 4096 tokens
#define GROUPS_ (NH_ / NKV_)    // 4
#define EPS_ 1e-6f

#define QKV_N_ 3072             // 2048 q + 512 k + 512 v
#define GU_N_  16384            // interleaved: col 2j=gate_j, 2j+1=up_j

// ---------------- scratch (device globals; no runtime allocation) ----------------
__device__ __half g_xnorm16[(size_t)M_ * H_];
__device__ __half g_q16[(size_t)B_ * NH_ * S_ * DH_];    // (b,h,s,d)
__device__ __half g_k16[(size_t)B_ * NKV_ * S_ * DH_];   // (b,kvh,s,d)
__device__ __half g_v16[(size_t)B_ * NKV_ * S_ * DH_];   // (b,kvh,s,d)
__device__ __half g_attn16[(size_t)M_ * H_];
__device__ float  g_h1[(size_t)M_ * H_];
__device__ __half g_x216[(size_t)M_ * H_];
__device__ __half g_act16[(size_t)M_ * I_];
// fp16 transposed weights: Wt[n][k] row-major
__device__ __half w_qkv[(size_t)QKV_N_ * H_];
__device__ __half w_o[(size_t)H_ * H_];
__device__ __half w_gu[(size_t)GU_N_ * H_];
__device__ __half w_dn[(size_t)H_ * I_];

// ---------------- helpers ----------------
__device__ __forceinline__ uint32_t smem_u32(const void* p) {
    return (uint32_t)__cvta_generic_to_shared(p);
}
__device__ __forceinline__ void cp_async16(uint32_t dst, const void* src) {
    asm volatile("cp.async.cg.shared.global [%0], [%1], 16;\n" :: "r"(dst), "l"(src));
}
__device__ __forceinline__ void cp_commit() { asm volatile("cp.async.commit_group;\n"); }
__device__ __forceinline__ void cp_wait0()  { asm volatile("cp.async.wait_group 0;\n"); }
__device__ __forceinline__ void cp_wait1()  { asm volatile("cp.async.wait_group 1;\n"); }

__device__ __forceinline__ void mma_f16(float* d, const uint32_t* a, uint32_t b0, uint32_t b1) {
    asm volatile(
        "mma.sync.aligned.m16n8k16.row.col.f32.f16.f16.f32 "
        "{%0,%1,%2,%3}, {%4,%5,%6,%7}, {%8,%9}, {%0,%1,%2,%3};\n"
        : "+f"(d[0]), "+f"(d[1]), "+f"(d[2]), "+f"(d[3])
        : "r"(a[0]), "r"(a[1]), "r"(a[2]), "r"(a[3]), "r"(b0), "r"(b1));
}

__device__ __forceinline__ uint32_t packh(float a, float b) {
    __half2 h = __floats2half2_rn(a, b);
    return *(uint32_t*)&h;
}

// ---------------- ALL weight transposes in ONE launch ----------------
__global__ __launch_bounds__(256) void transpose_all(
    const float* __restrict__ wq, const float* __restrict__ wk, const float* __restrict__ wv,
    const float* __restrict__ wo, const float* __restrict__ wg, const float* __restrict__ wu,
    const float* __restrict__ wd,
    __half* __restrict__ Wqkv, __half* __restrict__ Wo,
    __half* __restrict__ Wgu, __half* __restrict__ Wdn) {
    int bid = blockIdx.x;
    const float* src; __half* dst;
    int K, N, rowOff, rmul, bx, by;
    if (bid < 1024)       { src = wq; dst = Wqkv; K = 2048; N = 2048; rowOff = 0;    rmul = 1; int l = bid;         bx = l & 31;  by = l >> 5; }
    else if (bid < 1280)  { src = wk; dst = Wqkv; K = 2048; N = 512;  rowOff = 2048; rmul = 1; int l = bid - 1024;  bx = l & 7;   by = l >> 3; }
    else if (bid < 1536)  { src = wv; dst = Wqkv; K = 2048; N = 512;  rowOff = 2560; rmul = 1; int l = bid - 1280;  bx = l & 7;   by = l >> 3; }
    else if (bid < 2560)  { src = wo; dst = Wo;   K = 2048; N = 2048; rowOff = 0;    rmul = 1; int l = bid - 1536;  bx = l & 31;  by = l >> 5; }
    else if (bid < 6656)  { src = wg; dst = Wgu;  K = 2048; N = 8192; rowOff = 0;    rmul = 2; int l = bid - 2560;  bx = l & 127; by = l >> 7; }
    else if (bid < 10752) { src = wu; dst = Wgu;  K = 2048; N = 8192; rowOff = 1;    rmul = 2; int l = bid - 6656;  bx = l & 127; by = l >> 7; }
    else                  { src = wd; dst = Wdn;  K = 8192; N = 2048; rowOff = 0;    rmul = 1; int l = bid - 10752; bx = l & 31;  by = l >> 5; }

    __shared__ float tile[64][65];
    long k0 = (long)by * 64, n0 = (long)bx * 64;
    int t = threadIdx.x;
    {
        int r = t >> 2, c = (t & 3) * 16;
        const float* s = src + (k0 + r) * N + n0 + c;
        #pragma unroll
        for (int i = 0; i < 4; i++) {
            float4 v = *(const float4*)(s + i * 4);
            tile[r][c + i * 4 + 0] = v.x; tile[r][c + i * 4 + 1] = v.y;
            tile[r][c + i * 4 + 2] = v.z; tile[r][c + i * 4 + 3] = v.w;
        }
    }
    __syncthreads();
    #pragma unroll
    for (int wv2 = 0; wv2 < 2; wv2++) {
        int n = (t >> 3) + wv2 * 32;
        int ks = (t & 7) * 8;
        uint2 lo, hi;
        lo.x = packh(tile[ks + 0][n], tile[ks + 1][n]);
        lo.y = packh(tile[ks + 2][n], tile[ks + 3][n]);
        hi.x = packh(tile[ks + 4][n], tile[ks + 5][n]);
        hi.y = packh(tile[ks + 6][n], tile[ks + 7][n]);
        uint4 o = make_uint4(lo.x, lo.y, hi.x, hi.y);
        *(uint4*)(dst + (long)(rowOff + (n0 + n) * rmul) * K + k0 + ks) = o;
    }
}
#define TRANSPOSE_BLOCKS 14848

// ---------------- RMSNorm: fp32 in, fp16 out ----------------
__global__ void rmsnorm_kernel(const float* __restrict__ x, const float* __restrict__ w,
                               __half* __restrict__ y, int Hdim) {
    int row = blockIdx.x;
    const float4* xr = (const float4*)(x + (size_t)row * Hdim);
    uint2* yr = (uint2*)(y + (size_t)row * Hdim);
    const float4* wv = (const float4*)w;
    int n4 = Hdim >> 2;

    float ss = 0.f;
    for (int i = threadIdx.x; i < n4; i += blockDim.x) {
        float4 v = xr[i];
        ss += v.x * v.x + v.y * v.y + v.z * v.z + v.w * v.w;
    }
    __shared__ float wsum[8];
    for (int o = 16; o > 0; o >>= 1) ss += __shfl_xor_sync(0xffffffffu, ss, o);
    int warp = threadIdx.x >> 5;
    if ((threadIdx.x & 31) == 0) wsum[warp] = ss;
    __syncthreads();
    __shared__ float s_inv;
    if (threadIdx.x == 0) {
        float t = 0.f;
        #pragma unroll
        for (int i = 0; i < 8; i++) t += wsum[i];
        s_inv = rsqrtf(t / (float)Hdim + EPS_);
    }
    __syncthreads();
    float inv = s_inv;
    for (int i = threadIdx.x; i < n4; i += blockDim.x) {
        float4 v = xr[i];
        float4 ww = wv[i];
        uint2 o;
        o.x = packh(v.x * inv * ww.x, v.y * inv * ww.y);
        o.y = packh(v.z * inv * ww.z, v.w * inv * ww.w);
        yr[i] = o;
    }
}

// ---------------- fused q/k RMSNorm + RoPE: one WARP per (token, head), in place ----------------
__global__ __launch_bounds__(256) void qknorm_rope_kernel(
        __half* __restrict__ q16, __half* __restrict__ k16,
        const float* __restrict__ qnw, const float* __restrict__ knw,
        const float* __restrict__ cosp, const float* __restrict__ sinp) {
    int wid = threadIdx.x >> 5, lane = threadIdx.x & 31;
    int gw = blockIdx.x * 8 + wid;
    int hs = gw >> 12;
    int token = gw & 4095;
    int b = token >> 11, sq = token & 2047;

    __half* p;
    const float* w;
    float outScale;
    if (hs < NH_) {
        p = q16 + (((size_t)b * NH_ + hs) * S_ + sq) * DH_;
        w = qnw; outScale = 0.08838834764831845f;
    } else {
        p = k16 + (((size_t)b * NKV_ + (hs - NH_)) * S_ + sq) * DH_;
        w = knw; outScale = 1.0f;
    }

    int d = lane * 4;
    uint2 raw = *(const uint2*)(p + d);
    __half2 h01 = *(__half2*)&raw.x;
    __half2 h23 = *(__half2*)&raw.y;
    float v0 = __half2float(__low2half(h01)), v1 = __half2float(__high2half(h01));
    float v2 = __half2float(__low2half(h23)), v3 = __half2float(__high2half(h23));

    float ss = v0 * v0 + v1 * v1 + v2 * v2 + v3 * v3;
    #pragma unroll
    for (int o = 16; o > 0; o >>= 1) ss += __shfl_xor_sync(0xffffffffu, ss, o);
    float inv = rsqrtf(ss * (1.0f / (float)DH_) + EPS_);

    float4 ww = *(const float4*)(w + d);
    float n0 = v0 * inv * ww.x, n1 = v1 * inv * ww.y;
    float n2 = v2 * inv * ww.z, n3 = v3 * inv * ww.w;

    float o0 = __shfl_xor_sync(0xffffffffu, n0, 16);
    float o1 = __shfl_xor_sync(0xffffffffu, n1, 16);
    float o2 = __shfl_xor_sync(0xffffffffu, n2, 16);
    float o3 = __shfl_xor_sync(0xffffffffu, n3, 16);
    float sign = (lane < 16) ? -1.0f : 1.0f;

    float4 cv = *(const float4*)(cosp + (size_t)token * DH_ + d);
    float4 sv = *(const float4*)(sinp + (size_t)token * DH_ + d);

    float r0 = (n0 * cv.x + sign * o0 * sv.x) * outScale;
    float r1 = (n1 * cv.y + sign * o1 * sv.y) * outScale;
    float r2 = (n2 * cv.z + sign * o2 * sv.z) * outScale;
    float r3 = (n3 * cv.w + sign * o3 * sv.w) * outScale;

    uint2 outp;
    outp.x = packh(r0, r1);
    outp.y = packh(r2, r3);
    *(uint2*)(p + d) = outp;
}

// ---------------- fp16 tensor-core GEMM: 256 thr, 128x256, BK=64, 3-stage ----------------
// mode 0: fp32 C (+opt Res). mode 1: interleaved silu -> C16 width N/2.
// mode 3: QKV head-major routing -> q16/k16/v16.
#define GPA 72
#define G_ASZ (128 * GPA)
#define G_BSZ (256 * GPA)
#define G_STAGE (G_ASZ + G_BSZ)
#define G_NSTAGE 3
#define GEMM_SMEM_BYTES (G_NSTAGE * G_STAGE * 2)   // 165888 B

__device__ __forceinline__ void gemm_issue(const __half* __restrict__ A, long K, long rowBase,
                                           const __half* __restrict__ Bt, long colBase,
                                           __half* As, __half* Bs, int tid, int k0) {
    {
        int r = tid >> 1, hf = tid & 1;
        uint32_t dst = smem_u32(As + r * GPA + hf * 32);
        const __half* src = A + (rowBase + r) * K + k0 + hf * 32;
        #pragma unroll
        for (int i = 0; i < 4; i++) cp_async16(dst + i * 16, src + i * 8);
    }
    #pragma unroll
    for (int p = 0; p < 8; p++) {
        int f = tid + p * 256;
        int n = f >> 3, kc = f & 7;
        cp_async16(smem_u32(Bs + n * GPA + kc * 8),
                   Bt + (colBase + n) * K + k0 + kc * 8);
    }
}

__device__ __forceinline__ void gemm_compute(const __half* As, const __half* Bs,
                                             int wm, int wn, int gid, int tig,
                                             float (&acc)[4][8][4]) {
    #pragma unroll
    for (int kk = 0; kk < 64; kk += 16) {
        uint32_t a[4][4];
        #pragma unroll
        for (int mi = 0; mi < 4; mi++) {
            const __half* ap = As + (wm + mi * 16 + gid) * GPA + kk + tig * 2;
            a[mi][0] = *(const uint32_t*)(ap);
            a[mi][1] = *(const uint32_t*)(ap + 8 * GPA);
            a[mi][2] = *(const uint32_t*)(ap + 8);
            a[mi][3] = *(const uint32_t*)(ap + 8 * GPA + 8);
        }
        #pragma unroll
        for (int ni = 0; ni < 8; ni++) {
            const __half* bp = Bs + (wn + ni * 8 + gid) * GPA + kk + tig * 2;
            uint32_t b0 = *(const uint32_t*)(bp);
            uint32_t b1 = *(const uint32_t*)(bp + 8);
            #pragma unroll
            for (int mi = 0; mi < 4; mi++)
                mma_f16(acc[mi][ni], a[mi], b0, b1);
        }
    }
}

__device__ __forceinline__ float silu_mul(float g, float u) {
    return g / (1.f + __expf(-g)) * u;
}

__global__ __launch_bounds__(256, 1) void gemm_f16(const __half* __restrict__ A,
                                                   const __half* __restrict__ Bt,
                                                   const float* __restrict__ Res,
                                                   float* __restrict__ C,
                                                   __half* __restrict__ C16,
                                                   __half* __restrict__ Ck,
                                                   __half* __restrict__ Cv,
                                                   int N, int K, int mode) {
    extern __shared__ __half smh[];
    int tid = threadIdx.x;
    int wid = tid >> 5, lane = tid & 31;
    int gid = lane >> 2, tig = lane & 3;
    int wm = (wid >> 2) * 64, wn = (wid & 3) * 64;

    // CTA raster swizzle: 8-column groups for L2 locality
    int gx = gridDim.x, gy = gridDim.y;
    int bid = blockIdx.y * gx + blockIdx.x;
    int grpW = 8 * gy;
    int g8 = bid / grpW, r8 = bid % grpW;
    int wcols = min(8, gx - g8 * 8);
    int bxx = g8 * 8 + r8 % wcols;
    int byy = r8 / wcols;

    long rowBase = (long)byy * 128;
    long colBase = (long)bxx * 256;

    float acc[4][8][4] = {};

    __half* As[G_NSTAGE];
    __half* Bs[G_NSTAGE];
    #pragma unroll
    for (int s = 0; s < G_NSTAGE; s++) {
        As[s] = smh + s * G_STAGE;
        Bs[s] = As[s] + G_ASZ;
    }

    int nIter = K / 64;
    gemm_issue(A, K, rowBase, Bt, colBase, As[0], Bs[0], tid, 0);
    cp_commit();
    gemm_issue(A, K, rowBase, Bt, colBase, As[1], Bs[1], tid, 64);
    cp_commit();

    for (int it = 0; it < nIter; it++) {
        if (it + 1 < nIter) cp_wait1(); else cp_wait0();
        __syncthreads();
        if (it + 2 < nIter) {
            int s = (it + 2) % 3;
            gemm_issue(A, K, rowBase, Bt, colBase, As[s], Bs[s], tid, (it + 2) * 64);
            cp_commit();
        }
        gemm_compute(As[it % 3], Bs[it % 3], wm, wn, gid, tig, acc);
    }

    if (mode == 0) {
        #pragma unroll
        for (int mi = 0; mi < 4; mi++) {
            #pragma unroll
            for (int ni = 0; ni < 8; ni++) {
                long r0 = rowBase + wm + mi * 16 + gid;
                long c = colBase + wn + ni * 8 + tig * 2;
                float2 v0 = make_float2(acc[mi][ni][0], acc[mi][ni][1]);
                float2 v1 = make_float2(acc[mi][ni][2], acc[mi][ni][3]);
                if (Res != nullptr) {
                    float2 r0v = *(const float2*)(Res + r0 * N + c);
                    float2 r1v = *(const float2*)(Res + (r0 + 8) * N + c);
                    v0.x += r0v.x; v0.y += r0v.y;
                    v1.x += r1v.x; v1.y += r1v.y;
                }
                *(float2*)(C + r0 * N + c) = v0;
                *(float2*)(C + (r0 + 8) * N + c) = v1;
            }
        }
    } else if (mode == 1) {
        #pragma unroll
        for (int mi = 0; mi < 4; mi++) {
            #pragma unroll
            for (int ni = 0; ni < 8; ni++) {
                long r0 = rowBase + wm + mi * 16 + gid;
                long j = (colBase + wn + ni * 8 + tig * 2) >> 1;
                C16[r0 * (N / 2) + j] = __float2half_rn(silu_mul(acc[mi][ni][0], acc[mi][ni][1]));
                C16[(r0 + 8) * (N / 2) + j] = __float2half_rn(silu_mul(acc[mi][ni][2], acc[mi][ni][3]));
            }
        }
    } else {
        // mode 3: QKV head-major routing. C16 = q16, Ck = k16, Cv = v16.
        #pragma unroll
        for (int mi = 0; mi < 4; mi++) {
            #pragma unroll
            for (int ni = 0; ni < 8; ni++) {
                int c = (int)(colBase + wn + ni * 8 + tig * 2);
                #pragma unroll
                for (int half2i = 0; half2i < 2; half2i++) {
                    long tok = rowBase + wm + mi * 16 + gid + half2i * 8;
                    int b = (int)(tok >> 11), sq = (int)(tok & 2047);
                    uint32_t pk = packh(acc[mi][ni][half2i * 2], acc[mi][ni][half2i * 2 + 1]);
                    __half* dst;
                    if (c < 2048) {
                        int hh = c >> 7, d = c & 127;
                        dst = C16 + (((size_t)b * NH_ + hh) * S_ + sq) * DH_ + d;
                    } else if (c < 2560) {
                        int hh = (c - 2048) >> 7, d = c & 127;
                        dst = Ck + (((size_t)b * NKV_ + hh) * S_ + sq) * DH_ + d;
                    } else {
                        int hh = (c - 2560) >> 7, d = c & 127;
                        dst = Cv + (((size_t)b * NKV_ + hh) * S_ + sq) * DH_ + d;
                    }
                    *(uint32_t*)dst = pk;
                }
            }
        }
    }
}

// ---------------- fp16 flash attention: 64-row q blocks, 128 thr, 3 CTAs/SM ----------------
#define AST 136
#define AT_STAGE (2 * 64 * AST)
#define AT_SMEM_BYTES (2 * AT_STAGE * 2)     // 69632 B

__global__ __launch_bounds__(128, 3) void attn_kernel(const __half* __restrict__ q16,
                                                      const __half* __restrict__ k16,
                                                      const __half* __restrict__ v16,
                                                      __half* __restrict__ o) {
    extern __shared__ __half smh[];

    int qb = blockIdx.x, h = blockIdx.y, b = blockIdx.z;
    int kvh = h / GROUPS_;
    int tid = threadIdx.x;
    int w = tid >> 5, lane = tid & 31;
    int gid = lane >> 2, tig = lane & 3;
    int wq = w * 16;
    long bS = (long)b * S_;

    const __half* qh = q16 + (((size_t)b * NH_ + h) * S_ + (size_t)qb * 64) * DH_;
    const __half* kh = k16 + (((size_t)b * NKV_ + kvh) * S_) * DH_;
    const __half* vh = v16 + (((size_t)b * NKV_ + kvh) * S_) * DH_;

    __half* Qs = smh;
    for (int i = tid; i < 64 * 16; i += 128) {
        int r = i >> 4, c8 = (i & 15) * 8;
        *(uint4*)(Qs + r * AST + c8) = *(const uint4*)(qh + r * DH_ + c8);
    }
    __syncthreads();
    uint32_t qf[8][4];
    #pragma unroll
    for (int kk = 0; kk < 8; kk++) {
        const __half* qp = Qs + (wq + gid) * AST + kk * 16 + tig * 2;
        qf[kk][0] = *(const uint32_t*)(qp);
        qf[kk][1] = *(const uint32_t*)(qp + 8 * AST);
        qf[kk][2] = *(const uint32_t*)(qp + 8);
        qf[kk][3] = *(const uint32_t*)(qp + 8 * AST + 8);
    }
    __syncthreads();

    float of[16][4] = {};
    float m0 = -INFINITY, m1 = -INFINITY, l0 = 0.f, l1 = 0.f;

    int lrow = lane & 15, lsel = lane >> 4;

    {
        __half* Ks = smh;
        __half* Vs = smh + 64 * AST;
        #pragma unroll
        for (int p = 0; p < 8; p++) {
            int f = tid + p * 128;
            int r = f >> 4, c8 = (f & 15) * 8;
            cp_async16(smem_u32(Ks + r * AST + c8), kh + r * DH_ + c8);
            cp_async16(smem_u32(Vs + r * AST + c8), vh + r * DH_ + c8);
        }
        cp_commit();
    }

    const int nTiles = S_ / 64;
    for (int kt = 0; kt < nTiles; kt++) {
        if (kt + 1 < nTiles) {
            __half* Kn = smh + ((kt + 1) & 1) * AT_STAGE;
            __half* Vn = Kn + 64 * AST;
            const __half* kb = kh + (size_t)(kt + 1) * 64 * DH_;
            const __half* vb = vh + (size_t)(kt + 1) * 64 * DH_;
            #pragma unroll
            for (int p = 0; p < 8; p++) {
                int f = tid + p * 128;
                int r = f >> 4, c8 = (f & 15) * 8;
                cp_async16(smem_u32(Kn + r * AST + c8), kb + r * DH_ + c8);
                cp_async16(smem_u32(Vn + r * AST + c8), vb + r * DH_ + c8);
            }
            cp_commit();
            cp_wait1();
        } else {
            cp_wait0();
        }
        __syncthreads();

        const __half* Ks = smh + (kt & 1) * AT_STAGE;
        const __half* Vs = Ks + 64 * AST;

        float sc[8][4] = {};
        #pragma unroll
        for (int kk = 0; kk < 8; kk++) {
            #pragma unroll
            for (int ni = 0; ni < 8; ni++) {
                const __half* kp = Ks + (ni * 8 + gid) * AST + kk * 16 + tig * 2;
                uint32_t b0 = *(const uint32_t*)(kp);
                uint32_t b1 = *(const uint32_t*)(kp + 8);
                mma_f16(sc[ni], qf[kk], b0, b1);
            }
        }

        float mx0 = -INFINITY, mx1 = -INFINITY;
        #pragma unroll
        for (int ni = 0; ni < 8; ni++) {
            mx0 = fmaxf(mx0, fmaxf(sc[ni][0], sc[ni][1]));
            mx1 = fmaxf(mx1, fmaxf(sc[ni][2], sc[ni][3]));
        }
        mx0 = fmaxf(mx0, __shfl_xor_sync(0xffffffffu, mx0, 1));
        mx0 = fmaxf(mx0, __shfl_xor_sync(0xffffffffu, mx0, 2));
        mx1 = fmaxf(mx1, __shfl_xor_sync(0xffffffffu, mx1, 1));
        mx1 = fmaxf(mx1, __shfl_xor_sync(0xffffffffu, mx1, 2));
        float nm0 = fmaxf(m0, mx0), nm1 = fmaxf(m1, mx1);
        float s0 = 0.f, s1 = 0.f;
        #pragma unroll
        for (int ni = 0; ni < 8; ni++) {
            float e0 = __half2float(__float2half_rn(__expf(sc[ni][0] - nm0)));
            float e1 = __half2float(__float2half_rn(__expf(sc[ni][1] - nm0)));
            float e2 = __half2float(__float2half_rn(__expf(sc[ni][2] - nm1)));
            float e3 = __half2float(__float2half_rn(__expf(sc[ni][3] - nm1)));
            sc[ni][0] = e0; sc[ni][1] = e1; sc[ni][2] = e2; sc[ni][3] = e3;
            s0 += e0 + e1; s1 += e2 + e3;
        }
        s0 += __shfl_xor_sync(0xffffffffu, s0, 1);
        s0 += __shfl_xor_sync(0xffffffffu, s0, 2);
        s1 += __shfl_xor_sync(0xffffffffu, s1, 1);
        s1 += __shfl_xor_sync(0xffffffffu, s1, 2);
        float a0 = __expf(m0 - nm0), a1 = __expf(m1 - nm1);
        l0 = l0 * a0 + s0; l1 = l1 * a1 + s1;
        m0 = nm0; m1 = nm1;
        #pragma unroll
        for (int ni = 0; ni < 16; ni++) {
            of[ni][0] *= a0; of[ni][1] *= a0;
            of[ni][2] *= a1; of[ni][3] *= a1;
        }

        #pragma unroll
        for (int t = 0; t < 4; t++) {
            uint32_t pa[4];
            pa[0] = packh(sc[2 * t][0], sc[2 * t][1]);
            pa[1] = packh(sc[2 * t][2], sc[2 * t][3]);
            pa[2] = packh(sc[2 * t + 1][0], sc[2 * t + 1][1]);
            pa[3] = packh(sc[2 * t + 1][2], sc[2 * t + 1][3]);
            uint32_t vbase = smem_u32(Vs + (t * 16 + lrow) * AST + lsel * 8);
            #pragma unroll
            for (int ni2 = 0; ni2 < 8; ni2++) {
                uint32_t r0, r1, r2, r3;
                asm volatile(
                    "ldmatrix.sync.aligned.m8n8.x4.trans.shared.b16 {%0,%1,%2,%3}, [%4];"
                    : "=r"(r0), "=r"(r1), "=r"(r2), "=r"(r3)
                    : "r"(vbase + ni2 * 32u));
                mma_f16(of[2 * ni2], pa, r0, r1);
                mma_f16(of[2 * ni2 + 1], pa, r2, r3);
            }
        }
        __syncthreads();
    }

    float inv0 = 1.f / l0, inv1 = 1.f / l1;
    long r0 = bS + (long)qb * 64 + wq + gid;
    long r1 = r0 + 8;
    #pragma unroll
    for (int nt = 0; nt < 16; nt++) {
        int d = nt * 8 + tig * 2;
        *(uint32_t*)(o + (r0 * NH_ + h) * DH_ + d) = packh(of[nt][0] * inv0, of[nt][1] * inv0);
        *(uint32_t*)(o + (r1 * NH_ + h) * DH_ + d) = packh(of[nt][2] * inv1, of[nt][3] * inv1);
    }
}

// ---------------- launch ----------------
extern "C" void kernel_launch(void* const* d_in, const int* in_sizes, int n_in,
                              void* d_out, int out_size) {
    const float* hidden = (const float*)d_in[0];
    const float* cosp   = (const float*)d_in[1];
    const float* sinp   = (const float*)d_in[2];
    const float* wq     = (const float*)d_in[3];
    const float* wk     = (const float*)d_in[4];
    const float* wv     = (const float*)d_in[5];
    const float* wo     = (const float*)d_in[6];
    const float* qnw    = (const float*)d_in[7];
    const float* knw    = (const float*)d_in[8];
    const float* anw    = (const float*)d_in[9];
    const float* mnw    = (const float*)d_in[10];
    const float* wgate  = (const float*)d_in[11];
    const float* wup    = (const float*)d_in[12];
    const float* wdown  = (const float*)d_in[13];
    float* out = (float*)d_out;

    __half *xnorm, *q16, *k16, *v16, *attn, *x2, *act, *Wqkv, *Wo, *Wgu, *Wdn;
    float *h1;
    cudaGetSymbolAddress((void**)&xnorm, g_xnorm16);
    cudaGetSymbolAddress((void**)&q16, g_q16);
    cudaGetSymbolAddress((void**)&k16, g_k16);
    cudaGetSymbolAddress((void**)&v16, g_v16);
    cudaGetSymbolAddress((void**)&attn, g_attn16);
    cudaGetSymbolAddress((void**)&h1, g_h1);
    cudaGetSymbolAddress((void**)&x2, g_x216);
    cudaGetSymbolAddress((void**)&act, g_act16);
    cudaGetSymbolAddress((void**)&Wqkv, w_qkv);
    cudaGetSymbolAddress((void**)&Wo, w_o);
    cudaGetSymbolAddress((void**)&Wgu, w_gu);
    cudaGetSymbolAddress((void**)&Wdn, w_dn);

    cudaFuncSetAttribute(attn_kernel, cudaFuncAttributeMaxDynamicSharedMemorySize, AT_SMEM_BYTES);
    cudaFuncSetAttribute(gemm_f16, cudaFuncAttributeMaxDynamicSharedMemorySize, GEMM_SMEM_BYTES);

    // 0) ALL weight transposes in one launch
    transpose_all<<<TRANSPOSE_BLOCKS, 256>>>(wq, wk, wv, wo, wgate, wup, wdown,
                                             Wqkv, Wo, Wgu, Wdn);

    // 1) attn rmsnorm (fp16 out)
    rmsnorm_kernel<<<M_, 256>>>(hidden, anw, xnorm, H_);

    // 2) fused QKV projection -> head-major q16/k16/v16 directly (mode 3)
    gemm_f16<<<dim3(QKV_N_ / 256, M_ / 128), 256, GEMM_SMEM_BYTES>>>(
        xnorm, Wqkv, nullptr, nullptr, q16, k16, v16, QKV_N_, H_, 3);

    // 3) fused q/k norm + rope, warp-per-head, in place
    qknorm_rope_kernel<<<M_ * (NH_ + NKV_) / 8, 256>>>(q16, k16, qnw, knw, cosp, sinp);

    // 4) attention (fp16 mma, 64-row blocks, 3 CTAs/SM)
    attn_kernel<<<dim3(S_ / 64, NH_, B_), 128, AT_SMEM_BYTES>>>(q16, k16, v16, attn);

    // 5) O projection + residual (fp32 out)
    gemm_f16<<<dim3(H_ / 256, M_ / 128), 256, GEMM_SMEM_BYTES>>>(
        attn, Wo, hidden, h1, nullptr, nullptr, nullptr, H_, H_, 0);

    // 6) mlp rmsnorm (fp16 out)
    rmsnorm_kernel<<<M_, 256>>>(h1, mnw, x2, H_);

    // 7) fused gate+up projection, silu fused (fp16 act out)
    gemm_f16<<<dim3(GU_N_ / 256, M_ / 128), 256, GEMM_SMEM_BYTES>>>(
        x2, Wgu, nullptr, nullptr, act, nullptr, nullptr, GU_N_, H_, 1);

    // 8) down projection + residual -> output (fp32)
    gemm_f16<<<dim3(H_ / 256, M_ / 128), 256, GEMM_SMEM_BYTES>>>(
        act, Wdn, h1, out, nullptr, nullptr, nullptr, H_, I_, 0);
}

// round 17
// speedup vs baseline: 1.1184x; 1.0325x over previous
#include <cuda_runtime.h>
#include <cuda_fp16.h>
#include <math.h>
#include <stdint.h>

#define B_   2
#define S_   2048
#define H_   2048
#define NH_  16
#define NKV_ 4
#define DH_  128
#define I_   8192
#define M_   (B_ * S_)          // 4096 tokens
#define GROUPS_ (NH_ / NKV_)    // 4
#define EPS_ 1e-6f

#define QKV_N_ 3072             // 2048 q + 512 k + 512 v
#define GU_N_  16384            // interleaved: col 2j=gate_j, 2j+1=up_j

// ---------------- scratch (device globals; no runtime allocation) ----------------
__device__ __half g_xnorm16[(size_t)M_ * H_];
__device__ __half g_q16[(size_t)B_ * NH_ * S_ * DH_];    // (b,h,s,d)
__device__ __half g_k16[(size_t)B_ * NKV_ * S_ * DH_];   // (b,kvh,s,d)
__device__ __half g_v16[(size_t)B_ * NKV_ * S_ * DH_];   // (b,kvh,s,d)
__device__ __half g_attn16[(size_t)M_ * H_];
__device__ float  g_h1[(size_t)M_ * H_];
__device__ __half g_x216[(size_t)M_ * H_];
__device__ __half g_act16[(size_t)M_ * I_];
// fp16 transposed weights: Wt[n][k] row-major
__device__ __half w_qkv[(size_t)QKV_N_ * H_];
__device__ __half w_o[(size_t)H_ * H_];
__device__ __half w_gu[(size_t)GU_N_ * H_];
__device__ __half w_dn[(size_t)H_ * I_];

// ---------------- helpers ----------------
__device__ __forceinline__ uint32_t smem_u32(const void* p) {
    return (uint32_t)__cvta_generic_to_shared(p);
}
__device__ __forceinline__ void cp_async16(uint32_t dst, const void* src) {
    asm volatile("cp.async.cg.shared.global [%0], [%1], 16;\n" :: "r"(dst), "l"(src));
}
__device__ __forceinline__ void cp_commit() { asm volatile("cp.async.commit_group;\n"); }
__device__ __forceinline__ void cp_wait0()  { asm volatile("cp.async.wait_group 0;\n"); }
__device__ __forceinline__ void cp_wait1()  { asm volatile("cp.async.wait_group 1;\n"); }

__device__ __forceinline__ void mma_f16(float* d, const uint32_t* a, uint32_t b0, uint32_t b1) {
    asm volatile(
        "mma.sync.aligned.m16n8k16.row.col.f32.f16.f16.f32 "
        "{%0,%1,%2,%3}, {%4,%5,%6,%7}, {%8,%9}, {%0,%1,%2,%3};\n"
        : "+f"(d[0]), "+f"(d[1]), "+f"(d[2]), "+f"(d[3])
        : "r"(a[0]), "r"(a[1]), "r"(a[2]), "r"(a[3]), "r"(b0), "r"(b1));
}

__device__ __forceinline__ uint32_t packh(float a, float b) {
    __half2 h = __floats2half2_rn(a, b);
    return *(uint32_t*)&h;
}

// ---------------- fused pre-pass: ALL weight transposes + attn rmsnorm, ONE launch ----------------
#define TRANSPOSE_BLOCKS 14848
#define PREP_BLOCKS (TRANSPOSE_BLOCKS + M_)

__device__ __forceinline__ void rmsnorm_body(const float* __restrict__ x,
                                             const float* __restrict__ w,
                                             __half* __restrict__ y, int Hdim, int row,
                                             float* wsum) {
    const float4* xr = (const float4*)(x + (size_t)row * Hdim);
    uint2* yr = (uint2*)(y + (size_t)row * Hdim);
    const float4* wv = (const float4*)w;
    int n4 = Hdim >> 2;

    float ss = 0.f;
    for (int i = threadIdx.x; i < n4; i += blockDim.x) {
        float4 v = xr[i];
        ss += v.x * v.x + v.y * v.y + v.z * v.z + v.w * v.w;
    }
    for (int o = 16; o > 0; o >>= 1) ss += __shfl_xor_sync(0xffffffffu, ss, o);
    int warp = threadIdx.x >> 5;
    if ((threadIdx.x & 31) == 0) wsum[warp] = ss;
    __syncthreads();
    float inv;
    if (threadIdx.x == 0) {
        float t = 0.f;
        #pragma unroll
        for (int i = 0; i < 8; i++) t += wsum[i];
        wsum[0] = rsqrtf(t / (float)Hdim + EPS_);
    }
    __syncthreads();
    inv = wsum[0];
    for (int i = threadIdx.x; i < n4; i += blockDim.x) {
        float4 v = xr[i];
        float4 ww = wv[i];
        uint2 o;
        o.x = packh(v.x * inv * ww.x, v.y * inv * ww.y);
        o.y = packh(v.z * inv * ww.z, v.w * inv * ww.w);
        yr[i] = o;
    }
}

__global__ __launch_bounds__(256) void prep_all(
    const float* __restrict__ wq, const float* __restrict__ wk, const float* __restrict__ wv,
    const float* __restrict__ wo, const float* __restrict__ wg, const float* __restrict__ wu,
    const float* __restrict__ wd,
    __half* __restrict__ Wqkv, __half* __restrict__ Wo,
    __half* __restrict__ Wgu, __half* __restrict__ Wdn,
    const float* __restrict__ hidden, const float* __restrict__ anw,
    __half* __restrict__ xnorm) {
    __shared__ float tile[64][65];
    int bid = blockIdx.x;

    if (bid >= TRANSPOSE_BLOCKS) {
        rmsnorm_body(hidden, anw, xnorm, H_, bid - TRANSPOSE_BLOCKS, &tile[0][0]);
        return;
    }

    const float* src; __half* dst;
    int K, N, rowOff, rmul, bx, by;
    if (bid < 1024)       { src = wq; dst = Wqkv; K = 2048; N = 2048; rowOff = 0;    rmul = 1; int l = bid;         bx = l & 31;  by = l >> 5; }
    else if (bid < 1280)  { src = wk; dst = Wqkv; K = 2048; N = 512;  rowOff = 2048; rmul = 1; int l = bid - 1024;  bx = l & 7;   by = l >> 3; }
    else if (bid < 1536)  { src = wv; dst = Wqkv; K = 2048; N = 512;  rowOff = 2560; rmul = 1; int l = bid - 1280;  bx = l & 7;   by = l >> 3; }
    else if (bid < 2560)  { src = wo; dst = Wo;   K = 2048; N = 2048; rowOff = 0;    rmul = 1; int l = bid - 1536;  bx = l & 31;  by = l >> 5; }
    else if (bid < 6656)  { src = wg; dst = Wgu;  K = 2048; N = 8192; rowOff = 0;    rmul = 2; int l = bid - 2560;  bx = l & 127; by = l >> 7; }
    else if (bid < 10752) { src = wu; dst = Wgu;  K = 2048; N = 8192; rowOff = 1;    rmul = 2; int l = bid - 6656;  bx = l & 127; by = l >> 7; }
    else                  { src = wd; dst = Wdn;  K = 8192; N = 2048; rowOff = 0;    rmul = 1; int l = bid - 10752; bx = l & 31;  by = l >> 5; }

    long k0 = (long)by * 64, n0 = (long)bx * 64;
    int t = threadIdx.x;
    {
        int r = t >> 2, c = (t & 3) * 16;
        const float* s = src + (k0 + r) * N + n0 + c;
        #pragma unroll
        for (int i = 0; i < 4; i++) {
            float4 v = *(const float4*)(s + i * 4);
            tile[r][c + i * 4 + 0] = v.x; tile[r][c + i * 4 + 1] = v.y;
            tile[r][c + i * 4 + 2] = v.z; tile[r][c + i * 4 + 3] = v.w;
        }
    }
    __syncthreads();
    #pragma unroll
    for (int wv2 = 0; wv2 < 2; wv2++) {
        int n = (t >> 3) + wv2 * 32;
        int ks = (t & 7) * 8;
        uint2 lo, hi;
        lo.x = packh(tile[ks + 0][n], tile[ks + 1][n]);
        lo.y = packh(tile[ks + 2][n], tile[ks + 3][n]);
        hi.x = packh(tile[ks + 4][n], tile[ks + 5][n]);
        hi.y = packh(tile[ks + 6][n], tile[ks + 7][n]);
        uint4 o = make_uint4(lo.x, lo.y, hi.x, hi.y);
        *(uint4*)(dst + (long)(rowOff + (n0 + n) * rmul) * K + k0 + ks) = o;
    }
}

// ---------------- RMSNorm standalone (for mlp norm) ----------------
__global__ void rmsnorm_kernel(const float* __restrict__ x, const float* __restrict__ w,
                               __half* __restrict__ y, int Hdim) {
    __shared__ float wsum[8];
    rmsnorm_body(x, w, y, Hdim, blockIdx.x, wsum);
}

// ---------------- fused q/k RMSNorm + RoPE: one WARP per (token, head), in place ----------------
__global__ __launch_bounds__(256) void qknorm_rope_kernel(
        __half* __restrict__ q16, __half* __restrict__ k16,
        const float* __restrict__ qnw, const float* __restrict__ knw,
        const float* __restrict__ cosp, const float* __restrict__ sinp) {
    int wid = threadIdx.x >> 5, lane = threadIdx.x & 31;
    int gw = blockIdx.x * 8 + wid;
    int hs = gw >> 12;
    int token = gw & 4095;
    int b = token >> 11, sq = token & 2047;

    __half* p;
    const float* w;
    float outScale;
    if (hs < NH_) {
        p = q16 + (((size_t)b * NH_ + hs) * S_ + sq) * DH_;
        w = qnw; outScale = 0.08838834764831845f;
    } else {
        p = k16 + (((size_t)b * NKV_ + (hs - NH_)) * S_ + sq) * DH_;
        w = knw; outScale = 1.0f;
    }

    int d = lane * 4;
    uint2 raw = *(const uint2*)(p + d);
    __half2 h01 = *(__half2*)&raw.x;
    __half2 h23 = *(__half2*)&raw.y;
    float v0 = __half2float(__low2half(h01)), v1 = __half2float(__high2half(h01));
    float v2 = __half2float(__low2half(h23)), v3 = __half2float(__high2half(h23));

    float ss = v0 * v0 + v1 * v1 + v2 * v2 + v3 * v3;
    #pragma unroll
    for (int o = 16; o > 0; o >>= 1) ss += __shfl_xor_sync(0xffffffffu, ss, o);
    float inv = rsqrtf(ss * (1.0f / (float)DH_) + EPS_);

    float4 ww = *(const float4*)(w + d);
    float n0 = v0 * inv * ww.x, n1 = v1 * inv * ww.y;
    float n2 = v2 * inv * ww.z, n3 = v3 * inv * ww.w;

    float o0 = __shfl_xor_sync(0xffffffffu, n0, 16);
    float o1 = __shfl_xor_sync(0xffffffffu, n1, 16);
    float o2 = __shfl_xor_sync(0xffffffffu, n2, 16);
    float o3 = __shfl_xor_sync(0xffffffffu, n3, 16);
    float sign = (lane < 16) ? -1.0f : 1.0f;

    float4 cv = *(const float4*)(cosp + (size_t)token * DH_ + d);
    float4 sv = *(const float4*)(sinp + (size_t)token * DH_ + d);

    float r0 = (n0 * cv.x + sign * o0 * sv.x) * outScale;
    float r1 = (n1 * cv.y + sign * o1 * sv.y) * outScale;
    float r2 = (n2 * cv.z + sign * o2 * sv.z) * outScale;
    float r3 = (n3 * cv.w + sign * o3 * sv.w) * outScale;

    uint2 outp;
    outp.x = packh(r0, r1);
    outp.y = packh(r2, r3);
    *(uint2*)(p + d) = outp;
}

// ---------------- fp16 tensor-core GEMM: 256 thr, 128x256, BK=64, 3-stage ----------------
// mode 0: fp32 C (+opt Res). mode 1: interleaved silu -> C16 width N/2.
// mode 3: QKV head-major routing -> q16/k16/v16.
#define GPA 72
#define G_ASZ (128 * GPA)
#define G_BSZ (256 * GPA)
#define G_STAGE (G_ASZ + G_BSZ)
#define G_NSTAGE 3
#define GEMM_SMEM_BYTES (G_NSTAGE * G_STAGE * 2)   // 165888 B

__device__ __forceinline__ void gemm_issue(const __half* __restrict__ A, long K, long rowBase,
                                           const __half* __restrict__ Bt, long colBase,
                                           __half* As, __half* Bs, int tid, int k0) {
    {
        int r = tid >> 1, hf = tid & 1;
        uint32_t dst = smem_u32(As + r * GPA + hf * 32);
        const __half* src = A + (rowBase + r) * K + k0 + hf * 32;
        #pragma unroll
        for (int i = 0; i < 4; i++) cp_async16(dst + i * 16, src + i * 8);
    }
    #pragma unroll
    for (int p = 0; p < 8; p++) {
        int f = tid + p * 256;
        int n = f >> 3, kc = f & 7;
        cp_async16(smem_u32(Bs + n * GPA + kc * 8),
                   Bt + (colBase + n) * K + k0 + kc * 8);
    }
}

__device__ __forceinline__ void gemm_compute(const __half* As, const __half* Bs,
                                             int wm, int wn, int gid, int tig,
                                             float (&acc)[4][8][4]) {
    #pragma unroll
    for (int kk = 0; kk < 64; kk += 16) {
        uint32_t a[4][4];
        #pragma unroll
        for (int mi = 0; mi < 4; mi++) {
            const __half* ap = As + (wm + mi * 16 + gid) * GPA + kk + tig * 2;
            a[mi][0] = *(const uint32_t*)(ap);
            a[mi][1] = *(const uint32_t*)(ap + 8 * GPA);
            a[mi][2] = *(const uint32_t*)(ap + 8);
            a[mi][3] = *(const uint32_t*)(ap + 8 * GPA + 8);
        }
        #pragma unroll
        for (int ni = 0; ni < 8; ni++) {
            const __half* bp = Bs + (wn + ni * 8 + gid) * GPA + kk + tig * 2;
            uint32_t b0 = *(const uint32_t*)(bp);
            uint32_t b1 = *(const uint32_t*)(bp + 8);
            #pragma unroll
            for (int mi = 0; mi < 4; mi++)
                mma_f16(acc[mi][ni], a[mi], b0, b1);
        }
    }
}

__device__ __forceinline__ float silu_mul(float g, float u) {
    return g / (1.f + __expf(-g)) * u;
}

__global__ __launch_bounds__(256, 1) void gemm_f16(const __half* __restrict__ A,
                                                   const __half* __restrict__ Bt,
                                                   const float* __restrict__ Res,
                                                   float* __restrict__ C,
                                                   __half* __restrict__ C16,
                                                   __half* __restrict__ Ck,
                                                   __half* __restrict__ Cv,
                                                   int N, int K, int mode) {
    extern __shared__ __half smh[];
    int tid = threadIdx.x;
    int wid = tid >> 5, lane = tid & 31;
    int gid = lane >> 2, tig = lane & 3;
    int wm = (wid >> 2) * 64, wn = (wid & 3) * 64;

    // CTA raster swizzle: 8-column groups for L2 locality
    int gx = gridDim.x, gy = gridDim.y;
    int bid = blockIdx.y * gx + blockIdx.x;
    int grpW = 8 * gy;
    int g8 = bid / grpW, r8 = bid % grpW;
    int wcols = min(8, gx - g8 * 8);
    int bxx = g8 * 8 + r8 % wcols;
    int byy = r8 / wcols;

    long rowBase = (long)byy * 128;
    long colBase = (long)bxx * 256;

    float acc[4][8][4] = {};

    __half* As[G_NSTAGE];
    __half* Bs[G_NSTAGE];
    #pragma unroll
    for (int s = 0; s < G_NSTAGE; s++) {
        As[s] = smh + s * G_STAGE;
        Bs[s] = As[s] + G_ASZ;
    }

    int nIter = K / 64;
    gemm_issue(A, K, rowBase, Bt, colBase, As[0], Bs[0], tid, 0);
    cp_commit();
    gemm_issue(A, K, rowBase, Bt, colBase, As[1], Bs[1], tid, 64);
    cp_commit();

    for (int it = 0; it < nIter; it++) {
        if (it + 1 < nIter) cp_wait1(); else cp_wait0();
        __syncthreads();
        if (it + 2 < nIter) {
            int s = (it + 2) % 3;
            gemm_issue(A, K, rowBase, Bt, colBase, As[s], Bs[s], tid, (it + 2) * 64);
            cp_commit();
        }
        gemm_compute(As[it % 3], Bs[it % 3], wm, wn, gid, tig, acc);
    }

    if (mode == 0) {
        #pragma unroll
        for (int mi = 0; mi < 4; mi++) {
            #pragma unroll
            for (int ni = 0; ni < 8; ni++) {
                long r0 = rowBase + wm + mi * 16 + gid;
                long c = colBase + wn + ni * 8 + tig * 2;
                float2 v0 = make_float2(acc[mi][ni][0], acc[mi][ni][1]);
                float2 v1 = make_float2(acc[mi][ni][2], acc[mi][ni][3]);
                if (Res != nullptr) {
                    float2 r0v = *(const float2*)(Res + r0 * N + c);
                    float2 r1v = *(const float2*)(Res + (r0 + 8) * N + c);
                    v0.x += r0v.x; v0.y += r0v.y;
                    v1.x += r1v.x; v1.y += r1v.y;
                }
                *(float2*)(C + r0 * N + c) = v0;
                *(float2*)(C + (r0 + 8) * N + c) = v1;
            }
        }
    } else if (mode == 1) {
        #pragma unroll
        for (int mi = 0; mi < 4; mi++) {
            #pragma unroll
            for (int ni = 0; ni < 8; ni++) {
                long r0 = rowBase + wm + mi * 16 + gid;
                long j = (colBase + wn + ni * 8 + tig * 2) >> 1;
                C16[r0 * (N / 2) + j] = __float2half_rn(silu_mul(acc[mi][ni][0], acc[mi][ni][1]));
                C16[(r0 + 8) * (N / 2) + j] = __float2half_rn(silu_mul(acc[mi][ni][2], acc[mi][ni][3]));
            }
        }
    } else {
        // mode 3: QKV head-major routing. C16 = q16, Ck = k16, Cv = v16.
        #pragma unroll
        for (int mi = 0; mi < 4; mi++) {
            #pragma unroll
            for (int ni = 0; ni < 8; ni++) {
                int c = (int)(colBase + wn + ni * 8 + tig * 2);
                #pragma unroll
                for (int half2i = 0; half2i < 2; half2i++) {
                    long tok = rowBase + wm + mi * 16 + gid + half2i * 8;
                    int b = (int)(tok >> 11), sq = (int)(tok & 2047);
                    uint32_t pk = packh(acc[mi][ni][half2i * 2], acc[mi][ni][half2i * 2 + 1]);
                    __half* dst;
                    if (c < 2048) {
                        int hh = c >> 7, d = c & 127;
                        dst = C16 + (((size_t)b * NH_ + hh) * S_ + sq) * DH_ + d;
                    } else if (c < 2560) {
                        int hh = (c - 2048) >> 7, d = c & 127;
                        dst = Ck + (((size_t)b * NKV_ + hh) * S_ + sq) * DH_ + d;
                    } else {
                        int hh = (c - 2560) >> 7, d = c & 127;
                        dst = Cv + (((size_t)b * NKV_ + hh) * S_ + sq) * DH_ + d;
                    }
                    *(uint32_t*)dst = pk;
                }
            }
        }
    }
}

// ---------------- fp16 flash attention: 64-row q blocks, 128 thr, 2 CTAs/SM ----------------
#define AST 136
#define AT_STAGE (2 * 64 * AST)
#define AT_SMEM_BYTES (2 * AT_STAGE * 2)     // 69632 B

__global__ __launch_bounds__(128, 2) void attn_kernel(const __half* __restrict__ q16,
                                                      const __half* __restrict__ k16,
                                                      const __half* __restrict__ v16,
                                                      __half* __restrict__ o) {
    extern __shared__ __half smh[];

    int qb = blockIdx.x, h = blockIdx.y, b = blockIdx.z;
    int kvh = h / GROUPS_;
    int tid = threadIdx.x;
    int w = tid >> 5, lane = tid & 31;
    int gid = lane >> 2, tig = lane & 3;
    int wq = w * 16;
    long bS = (long)b * S_;

    const __half* qh = q16 + (((size_t)b * NH_ + h) * S_ + (size_t)qb * 64) * DH_;
    const __half* kh = k16 + (((size_t)b * NKV_ + kvh) * S_) * DH_;
    const __half* vh = v16 + (((size_t)b * NKV_ + kvh) * S_) * DH_;

    __half* Qs = smh;
    for (int i = tid; i < 64 * 16; i += 128) {
        int r = i >> 4, c8 = (i & 15) * 8;
        *(uint4*)(Qs + r * AST + c8) = *(const uint4*)(qh + r * DH_ + c8);
    }
    __syncthreads();
    uint32_t qf[8][4];
    #pragma unroll
    for (int kk = 0; kk < 8; kk++) {
        const __half* qp = Qs + (wq + gid) * AST + kk * 16 + tig * 2;
        qf[kk][0] = *(const uint32_t*)(qp);
        qf[kk][1] = *(const uint32_t*)(qp + 8 * AST);
        qf[kk][2] = *(const uint32_t*)(qp + 8);
        qf[kk][3] = *(const uint32_t*)(qp + 8 * AST + 8);
    }
    __syncthreads();

    float of[16][4] = {};
    float m0 = -INFINITY, m1 = -INFINITY, l0 = 0.f, l1 = 0.f;

    int lrow = lane & 15, lsel = lane >> 4;

    {
        __half* Ks = smh;
        __half* Vs = smh + 64 * AST;
        #pragma unroll
        for (int p = 0; p < 8; p++) {
            int f = tid + p * 128;
            int r = f >> 4, c8 = (f & 15) * 8;
            cp_async16(smem_u32(Ks + r * AST + c8), kh + r * DH_ + c8);
            cp_async16(smem_u32(Vs + r * AST + c8), vh + r * DH_ + c8);
        }
        cp_commit();
    }

    const int nTiles = S_ / 64;
    for (int kt = 0; kt < nTiles; kt++) {
        if (kt + 1 < nTiles) {
            __half* Kn = smh + ((kt + 1) & 1) * AT_STAGE;
            __half* Vn = Kn + 64 * AST;
            const __half* kb = kh + (size_t)(kt + 1) * 64 * DH_;
            const __half* vb = vh + (size_t)(kt + 1) * 64 * DH_;
            #pragma unroll
            for (int p = 0; p < 8; p++) {
                int f = tid + p * 128;
                int r = f >> 4, c8 = (f & 15) * 8;
                cp_async16(smem_u32(Kn + r * AST + c8), kb + r * DH_ + c8);
                cp_async16(smem_u32(Vn + r * AST + c8), vb + r * DH_ + c8);
            }
            cp_commit();
            cp_wait1();
        } else {
            cp_wait0();
        }
        __syncthreads();

        const __half* Ks = smh + (kt & 1) * AT_STAGE;
        const __half* Vs = Ks + 64 * AST;

        float sc[8][4] = {};
        #pragma unroll
        for (int kk = 0; kk < 8; kk++) {
            #pragma unroll
            for (int ni = 0; ni < 8; ni++) {
                const __half* kp = Ks + (ni * 8 + gid) * AST + kk * 16 + tig * 2;
                uint32_t b0 = *(const uint32_t*)(kp);
                uint32_t b1 = *(const uint32_t*)(kp + 8);
                mma_f16(sc[ni], qf[kk], b0, b1);
            }
        }

        float mx0 = -INFINITY, mx1 = -INFINITY;
        #pragma unroll
        for (int ni = 0; ni < 8; ni++) {
            mx0 = fmaxf(mx0, fmaxf(sc[ni][0], sc[ni][1]));
            mx1 = fmaxf(mx1, fmaxf(sc[ni][2], sc[ni][3]));
        }
        mx0 = fmaxf(mx0, __shfl_xor_sync(0xffffffffu, mx0, 1));
        mx0 = fmaxf(mx0, __shfl_xor_sync(0xffffffffu, mx0, 2));
        mx1 = fmaxf(mx1, __shfl_xor_sync(0xffffffffu, mx1, 1));
        mx1 = fmaxf(mx1, __shfl_xor_sync(0xffffffffu, mx1, 2));
        float nm0 = fmaxf(m0, mx0), nm1 = fmaxf(m1, mx1);
        float s0 = 0.f, s1 = 0.f;
        #pragma unroll
        for (int ni = 0; ni < 8; ni++) {
            float e0 = __half2float(__float2half_rn(__expf(sc[ni][0] - nm0)));
            float e1 = __half2float(__float2half_rn(__expf(sc[ni][1] - nm0)));
            float e2 = __half2float(__float2half_rn(__expf(sc[ni][2] - nm1)));
            float e3 = __half2float(__float2half_rn(__expf(sc[ni][3] - nm1)));
            sc[ni][0] = e0; sc[ni][1] = e1; sc[ni][2] = e2; sc[ni][3] = e3;
            s0 += e0 + e1; s1 += e2 + e3;
        }
        s0 += __shfl_xor_sync(0xffffffffu, s0, 1);
        s0 += __shfl_xor_sync(0xffffffffu, s0, 2);
        s1 += __shfl_xor_sync(0xffffffffu, s1, 1);
        s1 += __shfl_xor_sync(0xffffffffu, s1, 2);
        float a0 = __expf(m0 - nm0), a1 = __expf(m1 - nm1);
        l0 = l0 * a0 + s0; l1 = l1 * a1 + s1;
        m0 = nm0; m1 = nm1;
        #pragma unroll
        for (int ni = 0; ni < 16; ni++) {
            of[ni][0] *= a0; of[ni][1] *= a0;
            of[ni][2] *= a1; of[ni][3] *= a1;
        }

        #pragma unroll
        for (int t = 0; t < 4; t++) {
            uint32_t pa[4];
            pa[0] = packh(sc[2 * t][0], sc[2 * t][1]);
            pa[1] = packh(sc[2 * t][2], sc[2 * t][3]);
            pa[2] = packh(sc[2 * t + 1][0], sc[2 * t + 1][1]);
            pa[3] = packh(sc[2 * t + 1][2], sc[2 * t + 1][3]);
            uint32_t vbase = smem_u32(Vs + (t * 16 + lrow) * AST + lsel * 8);
            #pragma unroll
            for (int ni2 = 0; ni2 < 8; ni2++) {
                uint32_t r0, r1, r2, r3;
                asm volatile(
                    "ldmatrix.sync.aligned.m8n8.x4.trans.shared.b16 {%0,%1,%2,%3}, [%4];"
                    : "=r"(r0), "=r"(r1), "=r"(r2), "=r"(r3)
                    : "r"(vbase + ni2 * 32u));
                mma_f16(of[2 * ni2], pa, r0, r1);
                mma_f16(of[2 * ni2 + 1], pa, r2, r3);
            }
        }
        __syncthreads();
    }

    float inv0 = 1.f / l0, inv1 = 1.f / l1;
    long r0 = bS + (long)qb * 64 + wq + gid;
    long r1 = r0 + 8;
    #pragma unroll
    for (int nt = 0; nt < 16; nt++) {
        int d = nt * 8 + tig * 2;
        *(uint32_t*)(o + (r0 * NH_ + h) * DH_ + d) = packh(of[nt][0] * inv0, of[nt][1] * inv0);
        *(uint32_t*)(o + (r1 * NH_ + h) * DH_ + d) = packh(of[nt][2] * inv1, of[nt][3] * inv1);
    }
}

// ---------------- launch ----------------
extern "C" void kernel_launch(void* const* d_in, const int* in_sizes, int n_in,
                              void* d_out, int out_size) {
    const float* hidden = (const float*)d_in[0];
    const float* cosp   = (const float*)d_in[1];
    const float* sinp   = (const float*)d_in[2];
    const float* wq     = (const float*)d_in[3];
    const float* wk     = (const float*)d_in[4];
    const float* wv     = (const float*)d_in[5];
    const float* wo     = (const float*)d_in[6];
    const float* qnw    = (const float*)d_in[7];
    const float* knw    = (const float*)d_in[8];
    const float* anw    = (const float*)d_in[9];
    const float* mnw    = (const float*)d_in[10];
    const float* wgate  = (const float*)d_in[11];
    const float* wup    = (const float*)d_in[12];
    const float* wdown  = (const float*)d_in[13];
    float* out = (float*)d_out;

    __half *xnorm, *q16, *k16, *v16, *attn, *x2, *act, *Wqkv, *Wo, *Wgu, *Wdn;
    float *h1;
    cudaGetSymbolAddress((void**)&xnorm, g_xnorm16);
    cudaGetSymbolAddress((void**)&q16, g_q16);
    cudaGetSymbolAddress((void**)&k16, g_k16);
    cudaGetSymbolAddress((void**)&v16, g_v16);
    cudaGetSymbolAddress((void**)&attn, g_attn16);
    cudaGetSymbolAddress((void**)&h1, g_h1);
    cudaGetSymbolAddress((void**)&x2, g_x216);
    cudaGetSymbolAddress((void**)&act, g_act16);
    cudaGetSymbolAddress((void**)&Wqkv, w_qkv);
    cudaGetSymbolAddress((void**)&Wo, w_o);
    cudaGetSymbolAddress((void**)&Wgu, w_gu);
    cudaGetSymbolAddress((void**)&Wdn, w_dn);

    cudaFuncSetAttribute(attn_kernel, cudaFuncAttributeMaxDynamicSharedMemorySize, AT_SMEM_BYTES);
    cudaFuncSetAttribute(gemm_f16, cudaFuncAttributeMaxDynamicSharedMemorySize, GEMM_SMEM_BYTES);

    // 0) fused pre-pass: weight transposes + attn rmsnorm (concurrent, one launch)
    prep_all<<<PREP_BLOCKS, 256>>>(wq, wk, wv, wo, wgate, wup, wdown,
                                   Wqkv, Wo, Wgu, Wdn, hidden, anw, xnorm);

    // 1) fused QKV projection -> head-major q16/k16/v16 directly (mode 3)
    gemm_f16<<<dim3(QKV_N_ / 256, M_ / 128), 256, GEMM_SMEM_BYTES>>>(
        xnorm, Wqkv, nullptr, nullptr, q16, k16, v16, QKV_N_, H_, 3);

    // 2) fused q/k norm + rope, warp-per-head, in place
    qknorm_rope_kernel<<<M_ * (NH_ + NKV_) / 8, 256>>>(q16, k16, qnw, knw, cosp, sinp);

    // 3) attention (fp16 mma, 64-row blocks, 2 CTAs/SM)
    attn_kernel<<<dim3(S_ / 64, NH_, B_), 128, AT_SMEM_BYTES>>>(q16, k16, v16, attn);

    // 4) O projection + residual (fp32 out)
    gemm_f16<<<dim3(H_ / 256, M_ / 128), 256, GEMM_SMEM_BYTES>>>(
        attn, Wo, hidden, h1, nullptr, nullptr, nullptr, H_, H_, 0);

    // 5) mlp rmsnorm (fp16 out)
    rmsnorm_kernel<<<M_, 256>>>(h1, mnw, x2, H_);

    // 6) fused gate+up projection, silu fused (fp16 act out)
    gemm_f16<<<dim3(GU_N_ / 256, M_ / 128), 256, GEMM_SMEM_BYTES>>>(
        x2, Wgu, nullptr, nullptr, act, nullptr, nullptr, GU_N_, H_, 1);

    // 7) down projection + residual -> output (fp32)
    gemm_f16<<<dim3(H_ / 256, M_ / 128), 256, GEMM_SMEM_BYTES>>>(
        act, Wdn, h1, out, nullptr, nullptr, nullptr, H_, I_, 0);
}